// round 8
// baseline (speedup 1.0000x reference)
#include <cuda_runtime.h>
#include <cstdint>
#include <cstddef>

// Problem: x [32, 1, 8192, 256] fp32
//   out = maxpool_h(x, k=3, s=2, pad=1)       -> [32, 1, 4096, 256]
//   per-batch: (out - min) / (max - min)
//
// Pipelined two-pass-over-L2 plan (no DRAM intermediate; DRAM read of next
// chunk overlapped with L2-bound normalize of current chunk). Chunk = 4
// batches (33.6MB) so fused-phase L2 demand is 2x33.6=67MB << 126MB L2.
//   init
//   minmax(chunk0)                 : DRAM read, L2-retain, min/max reduce
//   fused(c -> c+1), c = 0..6      : normalize chunk c (L2 hits, __ldcs) +
//                                    minmax chunk c+1 (DRAM read, retain)
//   norm(chunk7)                   : normalize last chunk (L2 hits)
// DRAM ~ 268MB in + 134MB out = 402MB (information floor).

#define B_    32
#define H_IN  8192
#define H_OUT 4096
#define W4_   64              // float4 per row
#define CH_   16              // output rows per thread
#define ROWS_PER_BLOCK 64     // 4 sub-strips * CH_
#define BATCHES_PER_CHUNK 4
#define NCHUNKS (B_ / BATCHES_PER_CHUNK)                                 // 8
#define BLOCKS_PER_CHUNK (BATCHES_PER_CHUNK * (H_OUT / ROWS_PER_BLOCK))  // 256

__device__ unsigned int g_mn[B_];
__device__ unsigned int g_mx[B_];

// Orderable-uint encoding of float (total order matches float order):
// nonneg: u | 0x80000000 ; negative: ~u
__device__ __forceinline__ unsigned int f2o(float f) {
    unsigned int u = __float_as_uint(f);
    return (u & 0x80000000u) ? ~u : (u | 0x80000000u);
}
__device__ __forceinline__ float o2f(unsigned int e) {
    return __uint_as_float((e & 0x80000000u) ? (e & 0x7FFFFFFFu) : ~e);
}

__global__ void init_minmax_kernel() {
    int i = threadIdx.x;
    if (i < B_) {
        g_mn[i] = 0xFFFFFFFFu;  // min identity (encoded +max)
        g_mx[i] = 0x00000000u;  // max identity (encoded -max)
    }
}

__device__ __forceinline__ float4 fmax4(float4 a, float4 b) {
    float4 r;
    r.x = fmaxf(a.x, b.x); r.y = fmaxf(a.y, b.y);
    r.z = fmaxf(a.z, b.z); r.w = fmaxf(a.w, b.w);
    return r;
}

// Strip geometry shared by all kernels.
struct Strip {
    int b_off;   // batch within chunk
    int h0;      // first output row of this thread's strip
    int w4;      // float4 column
};
__device__ __forceinline__ Strip strip_of(int blk, int tid) {
    Strip s;
    s.w4 = tid & 63;
    const int sub = tid >> 6;
    s.b_off = blk >> 6;                 // 64 blocks per batch
    s.h0 = (blk & 63) * ROWS_PER_BLOCK + sub * CH_;
    return s;
}

// Block-level min/max reduce + atomics for batch b.
__device__ __forceinline__ void reduce_minmax(float lmn, float lmx, int b, int tid) {
    #pragma unroll
    for (int off = 16; off > 0; off >>= 1) {
        lmn = fminf(lmn, __shfl_xor_sync(0xFFFFFFFFu, lmn, off));
        lmx = fmaxf(lmx, __shfl_xor_sync(0xFFFFFFFFu, lmx, off));
    }
    __shared__ float s_mn[8];
    __shared__ float s_mx[8];
    const int lane = tid & 31;
    const int wid  = tid >> 5;
    if (lane == 0) { s_mn[wid] = lmn; s_mx[wid] = lmx; }
    __syncthreads();
    if (wid == 0) {
        lmn = (lane < 8) ? s_mn[lane] : __int_as_float(0x7f800000);
        lmx = (lane < 8) ? s_mx[lane] : __int_as_float(0xff800000);
        #pragma unroll
        for (int off = 4; off > 0; off >>= 1) {
            lmn = fminf(lmn, __shfl_xor_sync(0xFFFFFFFFu, lmn, off));
            lmx = fmaxf(lmx, __shfl_xor_sync(0xFFFFFFFFu, lmx, off));
        }
        if (lane == 0) {
            atomicMin(&g_mn[b], f2o(lmn));
            atomicMax(&g_mx[b], f2o(lmx));
        }
    }
}

// ---------------- minmax only (first chunk) ----------------
__global__ __launch_bounds__(256) void pool_minmax_kernel(
    const float* __restrict__ x, int b0)
{
    const int tid = threadIdx.x;
    const Strip s = strip_of(blockIdx.x, tid);
    const int b = b0 + s.b_off;

    const float4* __restrict__ xin =
        reinterpret_cast<const float4*>(x) + (size_t)b * H_IN * W4_ + s.w4;

    const float NEG_INF = __int_as_float(0xff800000);
    float4 prev;
    const int hi0 = 2 * s.h0 - 1;
    prev = (hi0 < 0) ? make_float4(NEG_INF, NEG_INF, NEG_INF, NEG_INF)
                     : xin[(size_t)hi0 * W4_];          // retain in L2

    float lmn = __int_as_float(0x7f800000);
    float lmx = NEG_INF;

    #pragma unroll
    for (int r = 0; r < CH_; r++) {
        const size_t base = (size_t)(2 * (s.h0 + r)) * W4_;
        float4 c = xin[base];                           // retain in L2
        float4 n = xin[base + W4_];
        float4 v = fmax4(fmax4(prev, c), n);
        lmn = fminf(lmn, fminf(fminf(v.x, v.y), fminf(v.z, v.w)));
        lmx = fmaxf(lmx, fmaxf(fmaxf(v.x, v.y), fmaxf(v.z, v.w)));
        prev = n;
    }
    reduce_minmax(lmn, lmx, b, tid);
}

// ---------------- normalize only (last chunk) ----------------
__global__ __launch_bounds__(256) void pool_norm_kernel(
    const float* __restrict__ x, float* __restrict__ out, int b0)
{
    const int tid = threadIdx.x;
    const Strip s = strip_of(blockIdx.x, tid);
    const int b = b0 + s.b_off;

    const float4* __restrict__ xin =
        reinterpret_cast<const float4*>(x) + (size_t)b * H_IN * W4_ + s.w4;
    float4* __restrict__ o =
        reinterpret_cast<float4*>(out) + ((size_t)b * H_OUT + s.h0) * W4_ + s.w4;

    const float NEG_INF = __int_as_float(0xff800000);
    const float mn  = o2f(g_mn[b]);
    const float mx  = o2f(g_mx[b]);
    const float inv = 1.0f / (mx - mn);

    float4 prev;
    const int hi0 = 2 * s.h0 - 1;
    prev = (hi0 < 0) ? make_float4(NEG_INF, NEG_INF, NEG_INF, NEG_INF)
                     : __ldcs(&xin[(size_t)hi0 * W4_]);  // last use

    #pragma unroll
    for (int r = 0; r < CH_; r++) {
        const size_t base = (size_t)(2 * (s.h0 + r)) * W4_;
        float4 c = __ldcs(&xin[base]);                   // last use (L2 hit)
        float4 n = __ldcs(&xin[base + W4_]);
        float4 v = fmax4(fmax4(prev, c), n);
        v.x = (v.x - mn) * inv;
        v.y = (v.y - mn) * inv;
        v.z = (v.z - mn) * inv;
        v.w = (v.w - mn) * inv;
        __stcs(&o[(size_t)r * W4_], v);                  // never re-read
        prev = n;
    }
}

// ------- fused: normalize chunk c (L2) + minmax chunk c+1 (DRAM) -------
__global__ __launch_bounds__(256) void fused_norm_minmax_kernel(
    const float* __restrict__ x, float* __restrict__ out,
    int b0_norm, int b0_mm)
{
    const int tid = threadIdx.x;
    const Strip s = strip_of(blockIdx.x, tid);
    const int bn = b0_norm + s.b_off;   // batch to normalize
    const int bm = b0_mm   + s.b_off;   // batch to reduce

    const float4* __restrict__ xn =
        reinterpret_cast<const float4*>(x) + (size_t)bn * H_IN * W4_ + s.w4;
    const float4* __restrict__ xm =
        reinterpret_cast<const float4*>(x) + (size_t)bm * H_IN * W4_ + s.w4;
    float4* __restrict__ o =
        reinterpret_cast<float4*>(out) + ((size_t)bn * H_OUT + s.h0) * W4_ + s.w4;

    const float NEG_INF = __int_as_float(0xff800000);
    const float mn  = o2f(g_mn[bn]);
    const float mx  = o2f(g_mx[bn]);
    const float inv = 1.0f / (mx - mn);

    const int hi0 = 2 * s.h0 - 1;
    float4 prevN, prevM;
    if (hi0 < 0) {
        prevN = make_float4(NEG_INF, NEG_INF, NEG_INF, NEG_INF);
        prevM = prevN;
    } else {
        prevM = xm[(size_t)hi0 * W4_];            // DRAM stream first (long lat)
        prevN = __ldcs(&xn[(size_t)hi0 * W4_]);   // L2 stream second
    }

    float lmn = __int_as_float(0x7f800000);
    float lmx = NEG_INF;

    #pragma unroll
    for (int r = 0; r < CH_; r++) {
        const size_t base = (size_t)(2 * (s.h0 + r)) * W4_;

        // Issue long-latency DRAM loads first, then L2 loads, then consume.
        float4 cm = xm[base];                     // next chunk: DRAM, retain
        float4 nm = xm[base + W4_];
        float4 cn = __ldcs(&xn[base]);            // current chunk: L2, last use
        float4 nn = __ldcs(&xn[base + W4_]);

        // --- minmax stream (next chunk) ---
        float4 vm = fmax4(fmax4(prevM, cm), nm);
        lmn = fminf(lmn, fminf(fminf(vm.x, vm.y), fminf(vm.z, vm.w)));
        lmx = fmaxf(lmx, fmaxf(fmaxf(vm.x, vm.y), fmaxf(vm.z, vm.w)));
        prevM = nm;

        // --- normalize stream (current chunk) ---
        float4 vn = fmax4(fmax4(prevN, cn), nn);
        vn.x = (vn.x - mn) * inv;
        vn.y = (vn.y - mn) * inv;
        vn.z = (vn.z - mn) * inv;
        vn.w = (vn.w - mn) * inv;
        __stcs(&o[(size_t)r * W4_], vn);
        prevN = nn;
    }

    reduce_minmax(lmn, lmx, bm, tid);
}

extern "C" void kernel_launch(void* const* d_in, const int* in_sizes, int n_in,
                              void* d_out, int out_size) {
    const float* x = (const float*)d_in[0];
    float* out = (float*)d_out;
    (void)in_sizes; (void)n_in; (void)out_size;

    init_minmax_kernel<<<1, 32>>>();

    // Prologue: reduce chunk 0
    pool_minmax_kernel<<<BLOCKS_PER_CHUNK, 256>>>(x, 0);

    // Steady state: normalize chunk c while reducing chunk c+1
    for (int c = 0; c + 1 < NCHUNKS; c++) {
        fused_norm_minmax_kernel<<<BLOCKS_PER_CHUNK, 256>>>(
            x, out, c * BATCHES_PER_CHUNK, (c + 1) * BATCHES_PER_CHUNK);
    }

    // Epilogue: normalize last chunk
    pool_norm_kernel<<<BLOCKS_PER_CHUNK, 256>>>(x, out,
                                                (NCHUNKS - 1) * BATCHES_PER_CHUNK);
}

// round 13
// speedup vs baseline: 1.3013x; 1.3013x over previous
#include <cuda_runtime.h>
#include <cstdint>
#include <cstddef>

// Problem: x [32, 1, 8192, 256] fp32
//   out = maxpool_h(x, k=3, s=2, pad=1)       -> [32, 1, 4096, 256]
//   per-batch: (out - min) / (max - min)
//
// Pipelined two-pass-over-L2 plan. R8 profile: occ=21%, DRAM=46% -> latency
// bound. R9: 512 blocks/launch (CH_=8), launch_bounds(256,4) for 4 blocks/SM
// (32 warps/SM, single wave), depth-1 prefetch in fused loop for 2x MLP.
//   init
//   minmax(chunk0)                 : DRAM read, L2-retain, min/max reduce
//   fused(c -> c+1), c = 0..6      : normalize chunk c (L2 hits, __ldcs) +
//                                    minmax chunk c+1 (DRAM read, retain)
//   norm(chunk7)                   : normalize last chunk (L2 hits)
// DRAM ~ 285MB in + 134MB out ~ 420MB.

#define B_    32
#define H_IN  8192
#define H_OUT 4096
#define W4_   64              // float4 per row
#define CH_   8               // output rows per thread
#define ROWS_PER_BLOCK 32     // 4 sub-strips * CH_
#define BLOCKS_PER_BATCH (H_OUT / ROWS_PER_BLOCK)                        // 128
#define BATCHES_PER_CHUNK 4
#define NCHUNKS (B_ / BATCHES_PER_CHUNK)                                 // 8
#define BLOCKS_PER_CHUNK (BATCHES_PER_CHUNK * BLOCKS_PER_BATCH)          // 512

__device__ unsigned int g_mn[B_];
__device__ unsigned int g_mx[B_];

// Orderable-uint encoding of float (total order matches float order):
// nonneg: u | 0x80000000 ; negative: ~u
__device__ __forceinline__ unsigned int f2o(float f) {
    unsigned int u = __float_as_uint(f);
    return (u & 0x80000000u) ? ~u : (u | 0x80000000u);
}
__device__ __forceinline__ float o2f(unsigned int e) {
    return __uint_as_float((e & 0x80000000u) ? (e & 0x7FFFFFFFu) : ~e);
}

__global__ void init_minmax_kernel() {
    int i = threadIdx.x;
    if (i < B_) {
        g_mn[i] = 0xFFFFFFFFu;  // min identity (encoded +max)
        g_mx[i] = 0x00000000u;  // max identity (encoded -max)
    }
}

__device__ __forceinline__ float4 fmax4(float4 a, float4 b) {
    float4 r;
    r.x = fmaxf(a.x, b.x); r.y = fmaxf(a.y, b.y);
    r.z = fmaxf(a.z, b.z); r.w = fmaxf(a.w, b.w);
    return r;
}

// Strip geometry shared by all kernels.
struct Strip {
    int b_off;   // batch within chunk
    int h0;      // first output row of this thread's strip
    int w4;      // float4 column
};
__device__ __forceinline__ Strip strip_of(int blk, int tid) {
    Strip s;
    s.w4 = tid & 63;
    const int sub = tid >> 6;
    s.b_off = blk >> 7;                 // 128 blocks per batch
    s.h0 = (blk & 127) * ROWS_PER_BLOCK + sub * CH_;
    return s;
}

// Block-level min/max reduce + atomics for batch b.
__device__ __forceinline__ void reduce_minmax(float lmn, float lmx, int b, int tid) {
    #pragma unroll
    for (int off = 16; off > 0; off >>= 1) {
        lmn = fminf(lmn, __shfl_xor_sync(0xFFFFFFFFu, lmn, off));
        lmx = fmaxf(lmx, __shfl_xor_sync(0xFFFFFFFFu, lmx, off));
    }
    __shared__ float s_mn[8];
    __shared__ float s_mx[8];
    const int lane = tid & 31;
    const int wid  = tid >> 5;
    if (lane == 0) { s_mn[wid] = lmn; s_mx[wid] = lmx; }
    __syncthreads();
    if (wid == 0) {
        lmn = (lane < 8) ? s_mn[lane] : __int_as_float(0x7f800000);
        lmx = (lane < 8) ? s_mx[lane] : __int_as_float(0xff800000);
        #pragma unroll
        for (int off = 4; off > 0; off >>= 1) {
            lmn = fminf(lmn, __shfl_xor_sync(0xFFFFFFFFu, lmn, off));
            lmx = fmaxf(lmx, __shfl_xor_sync(0xFFFFFFFFu, lmx, off));
        }
        if (lane == 0) {
            atomicMin(&g_mn[b], f2o(lmn));
            atomicMax(&g_mx[b], f2o(lmx));
        }
    }
}

// ---------------- minmax only (first chunk) ----------------
__global__ __launch_bounds__(256, 4) void pool_minmax_kernel(
    const float* __restrict__ x, int b0)
{
    const int tid = threadIdx.x;
    const Strip s = strip_of(blockIdx.x, tid);
    const int b = b0 + s.b_off;

    const float4* __restrict__ xin =
        reinterpret_cast<const float4*>(x) + (size_t)b * H_IN * W4_ + s.w4;

    const float NEG_INF = __int_as_float(0xff800000);
    float4 prev;
    const int hi0 = 2 * s.h0 - 1;
    prev = (hi0 < 0) ? make_float4(NEG_INF, NEG_INF, NEG_INF, NEG_INF)
                     : xin[(size_t)hi0 * W4_];          // retain in L2

    float lmn = __int_as_float(0x7f800000);
    float lmx = NEG_INF;

    // depth-1 prefetch
    size_t base = (size_t)(2 * s.h0) * W4_;
    float4 c = xin[base];
    float4 n = xin[base + W4_];

    #pragma unroll
    for (int r = 0; r < CH_; r++) {
        float4 c2 = c, n2 = n;
        if (r + 1 < CH_) {
            const size_t b2 = (size_t)(2 * (s.h0 + r + 1)) * W4_;
            c2 = xin[b2];
            n2 = xin[b2 + W4_];
        }
        float4 v = fmax4(fmax4(prev, c), n);
        lmn = fminf(lmn, fminf(fminf(v.x, v.y), fminf(v.z, v.w)));
        lmx = fmaxf(lmx, fmaxf(fmaxf(v.x, v.y), fmaxf(v.z, v.w)));
        prev = n;
        c = c2; n = n2;
    }
    reduce_minmax(lmn, lmx, b, tid);
}

// ---------------- normalize only (last chunk) ----------------
__global__ __launch_bounds__(256, 4) void pool_norm_kernel(
    const float* __restrict__ x, float* __restrict__ out, int b0)
{
    const int tid = threadIdx.x;
    const Strip s = strip_of(blockIdx.x, tid);
    const int b = b0 + s.b_off;

    const float4* __restrict__ xin =
        reinterpret_cast<const float4*>(x) + (size_t)b * H_IN * W4_ + s.w4;
    float4* __restrict__ o =
        reinterpret_cast<float4*>(out) + ((size_t)b * H_OUT + s.h0) * W4_ + s.w4;

    const float NEG_INF = __int_as_float(0xff800000);
    const float mn  = o2f(g_mn[b]);
    const float mx  = o2f(g_mx[b]);
    const float inv = 1.0f / (mx - mn);

    float4 prev;
    const int hi0 = 2 * s.h0 - 1;
    prev = (hi0 < 0) ? make_float4(NEG_INF, NEG_INF, NEG_INF, NEG_INF)
                     : __ldcs(&xin[(size_t)hi0 * W4_]);  // last use

    size_t base = (size_t)(2 * s.h0) * W4_;
    float4 c = __ldcs(&xin[base]);
    float4 n = __ldcs(&xin[base + W4_]);

    #pragma unroll
    for (int r = 0; r < CH_; r++) {
        float4 c2 = c, n2 = n;
        if (r + 1 < CH_) {
            const size_t b2 = (size_t)(2 * (s.h0 + r + 1)) * W4_;
            c2 = __ldcs(&xin[b2]);
            n2 = __ldcs(&xin[b2 + W4_]);
        }
        float4 v = fmax4(fmax4(prev, c), n);
        v.x = (v.x - mn) * inv;
        v.y = (v.y - mn) * inv;
        v.z = (v.z - mn) * inv;
        v.w = (v.w - mn) * inv;
        __stcs(&o[(size_t)r * W4_], v);                  // never re-read
        prev = n;
        c = c2; n = n2;
    }
}

// ------- fused: normalize chunk c (L2) + minmax chunk c+1 (DRAM) -------
__global__ __launch_bounds__(256, 4) void fused_norm_minmax_kernel(
    const float* __restrict__ x, float* __restrict__ out,
    int b0_norm, int b0_mm)
{
    const int tid = threadIdx.x;
    const Strip s = strip_of(blockIdx.x, tid);
    const int bn = b0_norm + s.b_off;   // batch to normalize
    const int bm = b0_mm   + s.b_off;   // batch to reduce

    const float4* __restrict__ xn =
        reinterpret_cast<const float4*>(x) + (size_t)bn * H_IN * W4_ + s.w4;
    const float4* __restrict__ xm =
        reinterpret_cast<const float4*>(x) + (size_t)bm * H_IN * W4_ + s.w4;
    float4* __restrict__ o =
        reinterpret_cast<float4*>(out) + ((size_t)bn * H_OUT + s.h0) * W4_ + s.w4;

    const float NEG_INF = __int_as_float(0xff800000);
    const float mn  = o2f(g_mn[bn]);
    const float mx  = o2f(g_mx[bn]);
    const float inv = 1.0f / (mx - mn);

    const int hi0 = 2 * s.h0 - 1;
    float4 prevN, prevM;
    if (hi0 < 0) {
        prevN = make_float4(NEG_INF, NEG_INF, NEG_INF, NEG_INF);
        prevM = prevN;
    } else {
        prevM = xm[(size_t)hi0 * W4_];            // DRAM stream first (long lat)
        prevN = __ldcs(&xn[(size_t)hi0 * W4_]);   // L2 stream second
    }

    float lmn = __int_as_float(0x7f800000);
    float lmx = NEG_INF;

    // depth-1 prefetch of both streams
    size_t base = (size_t)(2 * s.h0) * W4_;
    float4 cm = xm[base];
    float4 nm = xm[base + W4_];
    float4 cn = __ldcs(&xn[base]);
    float4 nn = __ldcs(&xn[base + W4_]);

    #pragma unroll
    for (int r = 0; r < CH_; r++) {
        float4 cm2 = cm, nm2 = nm, cn2 = cn, nn2 = nn;
        if (r + 1 < CH_) {
            const size_t b2 = (size_t)(2 * (s.h0 + r + 1)) * W4_;
            cm2 = xm[b2];                 // next chunk: DRAM, retain in L2
            nm2 = xm[b2 + W4_];
            cn2 = __ldcs(&xn[b2]);        // current chunk: L2, last use
            nn2 = __ldcs(&xn[b2 + W4_]);
        }

        // --- minmax stream (next chunk) ---
        float4 vm = fmax4(fmax4(prevM, cm), nm);
        lmn = fminf(lmn, fminf(fminf(vm.x, vm.y), fminf(vm.z, vm.w)));
        lmx = fmaxf(lmx, fmaxf(fmaxf(vm.x, vm.y), fmaxf(vm.z, vm.w)));
        prevM = nm;

        // --- normalize stream (current chunk) ---
        float4 vn = fmax4(fmax4(prevN, cn), nn);
        vn.x = (vn.x - mn) * inv;
        vn.y = (vn.y - mn) * inv;
        vn.z = (vn.z - mn) * inv;
        vn.w = (vn.w - mn) * inv;
        __stcs(&o[(size_t)r * W4_], vn);
        prevN = nn;

        cm = cm2; nm = nm2; cn = cn2; nn = nn2;
    }

    reduce_minmax(lmn, lmx, bm, tid);
}

extern "C" void kernel_launch(void* const* d_in, const int* in_sizes, int n_in,
                              void* d_out, int out_size) {
    const float* x = (const float*)d_in[0];
    float* out = (float*)d_out;
    (void)in_sizes; (void)n_in; (void)out_size;

    init_minmax_kernel<<<1, 32>>>();

    // Prologue: reduce chunk 0
    pool_minmax_kernel<<<BLOCKS_PER_CHUNK, 256>>>(x, 0);

    // Steady state: normalize chunk c while reducing chunk c+1
    for (int c = 0; c + 1 < NCHUNKS; c++) {
        fused_norm_minmax_kernel<<<BLOCKS_PER_CHUNK, 256>>>(
            x, out, c * BATCHES_PER_CHUNK, (c + 1) * BATCHES_PER_CHUNK);
    }

    // Epilogue: normalize last chunk
    pool_norm_kernel<<<BLOCKS_PER_CHUNK, 256>>>(x, out,
                                                (NCHUNKS - 1) * BATCHES_PER_CHUNK);
}